// round 3
// baseline (speedup 1.0000x reference)
#include <cuda_runtime.h>
#include <cuda_bf16.h>

// Problem constants (fixed by the dataset)
#define BATCH 8
#define CH    256
#define NPTS  65536
#define HID   256
#define OUTC  8
#define TOPK  512

// Scratch (no cudaMalloc allowed)
__device__ float g_score[BATCH * NPTS];
__device__ int   g_topk_idx[BATCH * TOPK];

// ---------------- packed f32x2 helpers ----------------
__device__ __forceinline__ unsigned long long pack2(float lo, float hi) {
    unsigned long long r;
    asm("mov.b64 %0, {%1, %2};" : "=l"(r) : "f"(lo), "f"(hi));
    return r;
}
__device__ __forceinline__ void unpack2(unsigned long long v, float& lo, float& hi) {
    asm("mov.b64 {%0, %1}, %2;" : "=f"(lo), "=f"(hi) : "l"(v));
}
__device__ __forceinline__ void fma2(unsigned long long& d, unsigned long long a, unsigned long long b) {
    asm("fma.rn.f32x2 %0, %1, %2, %0;" : "+l"(d) : "l"(a), "l"(b));
}

// ---------------- Phase A: score GEMM ----------------
// FC1: strictly sequential ascending-k FMA chain per output (matches the
// single-accumulator chain used by cuBLAS big-tile SGEMM / Eigen / Triton-fp32).
// FC2 (score): skinny-N k-sliced emulation: 4 slices, slice z owns
// k in {16*i + 4z .. 16*i + 4z + 3} (float4-chunked, coalescing-natural),
// each slice a sequential ascending chain, combined ((s0+s1)+s2)+s3.
#define PTS 64
#define KT  16

__global__ void __launch_bounds__(256, 2)
score_kernel(const float* __restrict__ feat, const float* __restrict__ W1,
             const float* __restrict__ b1, const float* __restrict__ W2,
             const float* __restrict__ b2) {
    __shared__ float w1s[KT * 256];   // 16 KB
    __shared__ float fs[KT * PTS];    // 4 KB
    __shared__ float w2s[256];        // 1 KB : W2[:,7]
    extern __shared__ float hmat[];   // 256*64 floats = 64 KB (dynamic)

    const int tid = threadIdx.x;
    const int b = blockIdx.y;
    const int n0 = blockIdx.x * PTS;
    const int row = tid >> 4;   // hid group: hid in [row*16, row*16+16)
    const int col = tid & 15;   // pt group:  pt  in [col*4, col*4+4)

    w2s[tid] = W2[tid * OUTC + 7];

    unsigned long long acc[8][4];
#pragma unroll
    for (int i = 0; i < 8; i++)
#pragma unroll
        for (int j = 0; j < 4; j++) acc[i][j] = 0ULL;

    const float* fbase = feat + (size_t)b * CH * NPTS + n0;

    for (int k0 = 0; k0 < CH; k0 += KT) {
        __syncthreads();
        // stage W1 tile: KT x 256 = 1024 float4, 4 per thread
#pragma unroll
        for (int j = 0; j < 4; j++) {
            int idx = tid + j * 256;
            int kk = idx >> 6;            // /64 float4 per row
            int c4 = (idx & 63) << 2;
            *(float4*)&w1s[kk * 256 + c4] =
                *(const float4*)&W1[(size_t)(k0 + kk) * HID + c4];
        }
        // stage f tile: KT x 64 = 256 float4, 1 per thread
        {
            int kk = tid >> 4;
            int p4 = (tid & 15) << 2;
            *(float4*)&fs[kk * PTS + p4] =
                *(const float4*)&fbase[(size_t)(k0 + kk) * NPTS + p4];
        }
        __syncthreads();

#pragma unroll
        for (int kk = 0; kk < KT; kk++) {
            unsigned long long wp[8];
#pragma unroll
            for (int i = 0; i < 4; i++) {
                ulonglong2 v = *(const ulonglong2*)&w1s[kk * 256 + row * 16 + i * 4];
                wp[2 * i] = v.x;
                wp[2 * i + 1] = v.y;
            }
            float4 fq = *(const float4*)&fs[kk * PTS + col * 4];
            unsigned long long fv[4];
            fv[0] = pack2(fq.x, fq.x);
            fv[1] = pack2(fq.y, fq.y);
            fv[2] = pack2(fq.z, fq.z);
            fv[3] = pack2(fq.w, fq.w);
#pragma unroll
            for (int hp = 0; hp < 8; hp++)
#pragma unroll
                for (int tp = 0; tp < 4; tp++)
                    fma2(acc[hp][tp], wp[hp], fv[tp]);
        }
    }
    __syncthreads();

    // bias + relu -> hmat[hid][pt]
#pragma unroll
    for (int hp = 0; hp < 8; hp++) {
        int h0 = row * 16 + hp * 2;
        float b1a = b1[h0], b1b = b1[h0 + 1];
#pragma unroll
        for (int tp = 0; tp < 4; tp++) {
            float lo, hi;
            unpack2(acc[hp][tp], lo, hi);
            int pt = col * 4 + tp;
            hmat[(size_t)h0 * PTS + pt] = fmaxf(lo + b1a, 0.0f);
            hmat[(size_t)(h0 + 1) * PTS + pt] = fmaxf(hi + b1b, 0.0f);
        }
    }
    __syncthreads();

    // score: 4-slice skinny-N order, chunk=4 (float4), period=16.
    // slice z: k in {16*i + 4z + kk : i=0..15, kk=0..3}, sequential chain.
    // combine ((s0+s1)+s2)+s3, then +b2[7].
    if (tid < PTS) {
        float s[4];
#pragma unroll
        for (int z = 0; z < 4; z++) {
            float a = 0.0f;
#pragma unroll
            for (int i = 0; i < 16; i++) {
                int base = 16 * i + 4 * z;
#pragma unroll
                for (int kk = 0; kk < 4; kk++)
                    a = fmaf(hmat[(base + kk) * PTS + tid], w2s[base + kk], a);
            }
            s[z] = a;
        }
        float sc = ((s[0] + s[1]) + s[2]) + s[3];
        g_score[(size_t)b * NPTS + n0 + tid] = sc + b2[7];
    }
}

// ---------------- Phase B: exact top-512 per batch ----------------
__device__ __forceinline__ unsigned int fkey(float f) {
    unsigned int u = __float_as_uint(f);
    return (u & 0x80000000u) ? ~u : (u | 0x80000000u);
}

__global__ void topk_kernel() {
    const int b = blockIdx.x;
    const int tid = threadIdx.x;
    __shared__ unsigned int hist[256];
    __shared__ unsigned int sh_prefix, sh_need;
    __shared__ int cnt;
    __shared__ unsigned long long cand[4096];

    const float* sc = g_score + (size_t)b * NPTS;

    unsigned int prefix = 0, mask = 0, need = TOPK;
    for (int pass = 0; pass < 4; pass++) {
        int shift = 24 - 8 * pass;
        if (tid < 256) hist[tid] = 0;
        __syncthreads();
        for (int i = tid; i < NPTS; i += 1024) {
            unsigned int u = fkey(sc[i]);
            if ((u & mask) == prefix) atomicAdd(&hist[(u >> shift) & 0xFF], 1u);
        }
        __syncthreads();
        if (tid == 0) {
            unsigned int cum = 0;
            int v;
            for (v = 255; v > 0; v--) {
                if (cum + hist[v] >= need) break;
                cum += hist[v];
            }
            sh_prefix = prefix | ((unsigned int)v << shift);
            sh_need = need - cum;
        }
        __syncthreads();
        prefix = sh_prefix;
        need = sh_need;
        mask |= 0xFFu << shift;
        __syncthreads();
    }
    // prefix == exact key of the 512th-largest score
    if (tid == 0) cnt = 0;
    __syncthreads();
    for (int i = tid; i < NPTS; i += 1024) {
        unsigned int u = fkey(sc[i]);
        if (u >= prefix) {
            int p = atomicAdd(&cnt, 1);
            if (p < 4096)
                cand[p] = ((unsigned long long)u << 32) |
                          (unsigned long long)(0xFFFFFFFFu - (unsigned int)i);
        }
    }
    __syncthreads();
    int M = cnt < 4096 ? cnt : 4096;
    for (int i = tid; i < 4096; i += 1024)
        if (i >= M) cand[i] = 0ULL;
    __syncthreads();

    // bitonic sort ascending on composite (key, ~idx): top 512 at the tail
    for (unsigned int k = 2; k <= 4096; k <<= 1) {
        for (unsigned int j = k >> 1; j > 0; j >>= 1) {
            for (unsigned int i = tid; i < 4096; i += 1024) {
                unsigned int ixj = i ^ j;
                if (ixj > i) {
                    unsigned long long a = cand[i], c2 = cand[ixj];
                    bool up = ((i & k) == 0);
                    if ((a > c2) == up) { cand[i] = c2; cand[ixj] = a; }
                }
            }
            __syncthreads();
        }
    }
    if (tid < TOPK) {
        unsigned long long e = cand[4095 - tid];
        g_topk_idx[b * TOPK + tid] =
            (int)(0xFFFFFFFFu - (unsigned int)(e & 0xFFFFFFFFULL));
    }
}

// ---------------- Phase C: recompute full 8-channel MLP at selected points ----------------
// 512 blocks x 256 threads, 8 points per block.
__global__ void __launch_bounds__(256)
gather_kernel(const float* __restrict__ feat, const float* __restrict__ W1,
              const float* __restrict__ b1, const float* __restrict__ W2,
              const float* __restrict__ b2, float* __restrict__ out) {
    __shared__ float fcol[CH][8];
    __shared__ float hs[HID][8];
    __shared__ float w2s[HID * OUTC];
    __shared__ int nidx[8];

    const int tid = threadIdx.x;
    const int b = blockIdx.x >> 6;            // /64
    const int r0 = (blockIdx.x & 63) * 8;

    if (tid < 8) nidx[tid] = g_topk_idx[b * TOPK + r0 + tid];
    for (int i = tid; i < HID * OUTC; i += 256) w2s[i] = W2[i];
    __syncthreads();

#pragma unroll
    for (int p = 0; p < 8; p++)
        fcol[tid][p] = feat[((size_t)b * CH + tid) * NPTS + nidx[p]];
    __syncthreads();

    float acc[8];
#pragma unroll
    for (int p = 0; p < 8; p++) acc[p] = 0.0f;
    for (int c = 0; c < CH; c++) {
        float w = W1[(size_t)c * HID + tid];
#pragma unroll
        for (int p = 0; p < 8; p++) acc[p] = fmaf(fcol[c][p], w, acc[p]);
    }
    float b1v = b1[tid];
#pragma unroll
    for (int p = 0; p < 8; p++) hs[tid][p] = fmaxf(acc[p] + b1v, 0.0f);
    __syncthreads();

    if (tid < 64) {
        int p = tid >> 3, o = tid & 7;
        float a = 0.0f;
#pragma unroll 16
        for (int hh = 0; hh < HID; hh++)
            a = fmaf(hs[hh][p], w2s[hh * OUTC + o], a);
        out[((size_t)(b * TOPK + r0 + p)) * OUTC + o] = a + b2[o];
    }
}

// ---------------- launch ----------------
extern "C" void kernel_launch(void* const* d_in, const int* in_sizes, int n_in,
                              void* d_out, int out_size) {
    // inputs: 0 points(unused), 1 features, 2 W1, 3 b1, 4 W2, 5 b2, 6 topk
    const float* feat = (const float*)d_in[1];
    const float* W1 = (const float*)d_in[2];
    const float* b1 = (const float*)d_in[3];
    const float* W2 = (const float*)d_in[4];
    const float* b2 = (const float*)d_in[5];
    float* out = (float*)d_out;

    cudaFuncSetAttribute(score_kernel, cudaFuncAttributeMaxDynamicSharedMemorySize,
                         256 * PTS * (int)sizeof(float));

    dim3 gA(NPTS / PTS, BATCH);
    score_kernel<<<gA, 256, 256 * PTS * sizeof(float)>>>(feat, W1, b1, W2, b2);
    topk_kernel<<<BATCH, 1024>>>();
    gather_kernel<<<BATCH * (TOPK / 8), 256>>>(feat, W1, b1, W2, b2, out);
}

// round 4
// speedup vs baseline: 1.1472x; 1.1472x over previous
#include <cuda_runtime.h>
#include <cuda_bf16.h>

// Problem constants (fixed by the dataset)
#define BATCH 8
#define CH    256
#define NPTS  65536
#define HID   256
#define OUTC  8
#define TOPK  512

// Scratch (no cudaMalloc allowed)
__device__ float g_score[BATCH * NPTS];
__device__ int   g_topk_idx[BATCH * TOPK];

// ---------------- packed f32x2 helpers ----------------
__device__ __forceinline__ unsigned long long pack2(float lo, float hi) {
    unsigned long long r;
    asm("mov.b64 %0, {%1, %2};" : "=l"(r) : "f"(lo), "f"(hi));
    return r;
}
__device__ __forceinline__ void unpack2(unsigned long long v, float& lo, float& hi) {
    asm("mov.b64 {%0, %1}, %2;" : "=f"(lo), "=f"(hi) : "l"(v));
}
__device__ __forceinline__ void fma2(unsigned long long& d, unsigned long long a, unsigned long long b) {
    asm("fma.rn.f32x2 %0, %1, %2, %0;" : "+l"(d) : "l"(a), "l"(b));
}

// ---------------- cp.async helpers ----------------
__device__ __forceinline__ void cp16(void* dst_smem, const void* src) {
    unsigned s = (unsigned)__cvta_generic_to_shared(dst_smem);
    asm volatile("cp.async.cg.shared.global [%0], [%1], 16;" :: "r"(s), "l"(src));
}
__device__ __forceinline__ void cp_commit() {
    asm volatile("cp.async.commit_group;");
}
__device__ __forceinline__ void cp_wait1() {
    asm volatile("cp.async.wait_group 1;");
}
__device__ __forceinline__ void cp_wait0() {
    asm volatile("cp.async.wait_group 0;");
}

// ---------------- Phase A: score GEMM ----------------
// FC1: strictly sequential ascending-k FMA chain per output.
// FC2 (score): 4 slices, slice z owns k in {16*i + 4z .. 16*i + 4z + 3},
// each slice a sequential ascending chain, combined ((s0+s1)+s2)+s3.
// (This exact order passed with rel_err 2e-7 — do not change.)
#define PTS 64
#define KT  16
#define NK  (CH / KT)   // 16 k-tiles

__global__ void __launch_bounds__(256, 2)
score_kernel(const float* __restrict__ feat, const float* __restrict__ W1,
             const float* __restrict__ b1, const float* __restrict__ W2,
             const float* __restrict__ b2) {
    __shared__ float w1s[2][KT * 256];  // 2 x 16 KB
    __shared__ float fs[2][KT * PTS];   // 2 x 4 KB
    __shared__ float w2s[256];          // 1 KB : W2[:,7]
    extern __shared__ float hmat[];     // 256*64 floats = 64 KB (dynamic)

    const int tid = threadIdx.x;
    const int b = blockIdx.y;
    const int n0 = blockIdx.x * PTS;
    const int row = tid >> 4;   // hid group: hid in [row*16, row*16+16)
    const int col = tid & 15;   // pt group:  pt  in [col*4, col*4+4)

    w2s[tid] = W2[tid * OUTC + 7];

    const float* fbase = feat + (size_t)b * CH * NPTS + n0;

    // staging coordinates (per thread): 4 float4 of W1, 1 float4 of f
    const int wkk[4] = { (tid + 0) >> 6, (tid + 256) >> 6, (tid + 512) >> 6, (tid + 768) >> 6 };
    const int wc4 = (tid & 63) << 2;
    const int fkk_ = tid >> 4;
    const int fp4 = (tid & 15) << 2;

    // issue tile t into buffer buf
    auto issue = [&](int t, int buf) {
        const int k0 = t * KT;
#pragma unroll
        for (int j = 0; j < 4; j++)
            cp16(&w1s[buf][wkk[j] * 256 + wc4],
                 &W1[(size_t)(k0 + wkk[j]) * HID + wc4]);
        cp16(&fs[buf][fkk_ * PTS + fp4],
             &fbase[(size_t)(k0 + fkk_) * NPTS + fp4]);
        cp_commit();
    };

    unsigned long long acc[8][4];
#pragma unroll
    for (int i = 0; i < 8; i++)
#pragma unroll
        for (int j = 0; j < 4; j++) acc[i][j] = 0ULL;

    // depth-2 pipeline prologue
    issue(0, 0);
    issue(1, 1);

    int p = 0;
#pragma unroll 1
    for (int t = 0; t < NK; t++) {
        if (t + 1 < NK) cp_wait1(); else cp_wait0();
        __syncthreads();   // buf[p] fully staged across all threads

#pragma unroll
        for (int kk = 0; kk < KT; kk++) {
            unsigned long long wp[8];
#pragma unroll
            for (int i = 0; i < 4; i++) {
                ulonglong2 v = *(const ulonglong2*)&w1s[p][kk * 256 + row * 16 + i * 4];
                wp[2 * i] = v.x;
                wp[2 * i + 1] = v.y;
            }
            float4 fq = *(const float4*)&fs[p][kk * PTS + col * 4];
            unsigned long long fv[4];
            fv[0] = pack2(fq.x, fq.x);
            fv[1] = pack2(fq.y, fq.y);
            fv[2] = pack2(fq.z, fq.z);
            fv[3] = pack2(fq.w, fq.w);
#pragma unroll
            for (int hp = 0; hp < 8; hp++)
#pragma unroll
                for (int tp = 0; tp < 4; tp++)
                    fma2(acc[hp][tp], wp[hp], fv[tp]);
        }

        __syncthreads();   // all threads done reading buf[p] before reuse
        if (t + 2 < NK) issue(t + 2, p);
        p ^= 1;
    }

    // bias + relu -> hmat[hid][pt]
#pragma unroll
    for (int hp = 0; hp < 8; hp++) {
        int h0 = row * 16 + hp * 2;
        float b1a = b1[h0], b1b = b1[h0 + 1];
#pragma unroll
        for (int tp = 0; tp < 4; tp++) {
            float lo, hi;
            unpack2(acc[hp][tp], lo, hi);
            int pt = col * 4 + tp;
            hmat[(size_t)h0 * PTS + pt] = fmaxf(lo + b1a, 0.0f);
            hmat[(size_t)(h0 + 1) * PTS + pt] = fmaxf(hi + b1b, 0.0f);
        }
    }
    __syncthreads();

    // FC2 score: slice-parallel, 4 threads per point (z = tid>>6, pt = tid&63).
    // Each slice chain is bit-identical to the sequential version.
    float* ps = &w1s[0][0];   // reuse staging smem for partials: ps[z*64+pt]
    {
        const int z = tid >> 6;
        const int pt = tid & 63;
        float a = 0.0f;
#pragma unroll
        for (int i = 0; i < 16; i++) {
            int base = 16 * i + 4 * z;
#pragma unroll
            for (int kk = 0; kk < 4; kk++)
                a = fmaf(hmat[(base + kk) * PTS + pt], w2s[base + kk], a);
        }
        ps[tid] = a;
    }
    __syncthreads();

    if (tid < PTS) {
        float sc = ((ps[tid] + ps[64 + tid]) + ps[128 + tid]) + ps[192 + tid];
        g_score[(size_t)b * NPTS + n0 + tid] = sc + b2[7];
    }
}

// ---------------- Phase B: exact top-512 per batch ----------------
__device__ __forceinline__ unsigned int fkey(float f) {
    unsigned int u = __float_as_uint(f);
    return (u & 0x80000000u) ? ~u : (u | 0x80000000u);
}

__global__ void topk_kernel() {
    const int b = blockIdx.x;
    const int tid = threadIdx.x;
    __shared__ unsigned int hist[256];
    __shared__ unsigned int sh_prefix, sh_need;
    __shared__ int cnt;
    __shared__ unsigned long long cand[4096];

    const float* sc = g_score + (size_t)b * NPTS;

    unsigned int prefix = 0, mask = 0, need = TOPK;
    for (int pass = 0; pass < 4; pass++) {
        int shift = 24 - 8 * pass;
        if (tid < 256) hist[tid] = 0;
        __syncthreads();
        for (int i = tid; i < NPTS; i += 1024) {
            unsigned int u = fkey(sc[i]);
            if ((u & mask) == prefix) atomicAdd(&hist[(u >> shift) & 0xFF], 1u);
        }
        __syncthreads();
        if (tid == 0) {
            unsigned int cum = 0;
            int v;
            for (v = 255; v > 0; v--) {
                if (cum + hist[v] >= need) break;
                cum += hist[v];
            }
            sh_prefix = prefix | ((unsigned int)v << shift);
            sh_need = need - cum;
        }
        __syncthreads();
        prefix = sh_prefix;
        need = sh_need;
        mask |= 0xFFu << shift;
        __syncthreads();
    }
    // prefix == exact key of the 512th-largest score
    if (tid == 0) cnt = 0;
    __syncthreads();
    for (int i = tid; i < NPTS; i += 1024) {
        unsigned int u = fkey(sc[i]);
        if (u >= prefix) {
            int p = atomicAdd(&cnt, 1);
            if (p < 4096)
                cand[p] = ((unsigned long long)u << 32) |
                          (unsigned long long)(0xFFFFFFFFu - (unsigned int)i);
        }
    }
    __syncthreads();
    int M = cnt < 4096 ? cnt : 4096;
    for (int i = tid; i < 4096; i += 1024)
        if (i >= M) cand[i] = 0ULL;
    __syncthreads();

    // bitonic sort ascending on composite (key, ~idx): top 512 at the tail
    for (unsigned int k = 2; k <= 4096; k <<= 1) {
        for (unsigned int j = k >> 1; j > 0; j >>= 1) {
            for (unsigned int i = tid; i < 4096; i += 1024) {
                unsigned int ixj = i ^ j;
                if (ixj > i) {
                    unsigned long long a = cand[i], c2 = cand[ixj];
                    bool up = ((i & k) == 0);
                    if ((a > c2) == up) { cand[i] = c2; cand[ixj] = a; }
                }
            }
            __syncthreads();
        }
    }
    if (tid < TOPK) {
        unsigned long long e = cand[4095 - tid];
        g_topk_idx[b * TOPK + tid] =
            (int)(0xFFFFFFFFu - (unsigned int)(e & 0xFFFFFFFFULL));
    }
}

// ---------------- Phase C: recompute full 8-channel MLP at selected points ----------------
// 512 blocks x 256 threads, 8 points per block.
__global__ void __launch_bounds__(256)
gather_kernel(const float* __restrict__ feat, const float* __restrict__ W1,
              const float* __restrict__ b1, const float* __restrict__ W2,
              const float* __restrict__ b2, float* __restrict__ out) {
    __shared__ float fcol[CH][8];
    __shared__ float hs[HID][8];
    __shared__ float w2s[HID * OUTC];
    __shared__ int nidx[8];

    const int tid = threadIdx.x;
    const int b = blockIdx.x >> 6;            // /64
    const int r0 = (blockIdx.x & 63) * 8;

    if (tid < 8) nidx[tid] = g_topk_idx[b * TOPK + r0 + tid];
    for (int i = tid; i < HID * OUTC; i += 256) w2s[i] = W2[i];
    __syncthreads();

#pragma unroll
    for (int p = 0; p < 8; p++)
        fcol[tid][p] = feat[((size_t)b * CH + tid) * NPTS + nidx[p]];
    __syncthreads();

    float acc[8];
#pragma unroll
    for (int p = 0; p < 8; p++) acc[p] = 0.0f;
    for (int c = 0; c < CH; c++) {
        float w = W1[(size_t)c * HID + tid];
#pragma unroll
        for (int p = 0; p < 8; p++) acc[p] = fmaf(fcol[c][p], w, acc[p]);
    }
    float b1v = b1[tid];
#pragma unroll
    for (int p = 0; p < 8; p++) hs[tid][p] = fmaxf(acc[p] + b1v, 0.0f);
    __syncthreads();

    if (tid < 64) {
        int p = tid >> 3, o = tid & 7;
        float a = 0.0f;
#pragma unroll 16
        for (int hh = 0; hh < HID; hh++)
            a = fmaf(hs[hh][p], w2s[hh * OUTC + o], a);
        out[((size_t)(b * TOPK + r0 + p)) * OUTC + o] = a + b2[o];
    }
}

// ---------------- launch ----------------
extern "C" void kernel_launch(void* const* d_in, const int* in_sizes, int n_in,
                              void* d_out, int out_size) {
    // inputs: 0 points(unused), 1 features, 2 W1, 3 b1, 4 W2, 5 b2, 6 topk
    const float* feat = (const float*)d_in[1];
    const float* W1 = (const float*)d_in[2];
    const float* b1 = (const float*)d_in[3];
    const float* W2 = (const float*)d_in[4];
    const float* b2 = (const float*)d_in[5];
    float* out = (float*)d_out;

    cudaFuncSetAttribute(score_kernel, cudaFuncAttributeMaxDynamicSharedMemorySize,
                         256 * PTS * (int)sizeof(float));

    dim3 gA(NPTS / PTS, BATCH);
    score_kernel<<<gA, 256, 256 * PTS * sizeof(float)>>>(feat, W1, b1, W2, b2);
    topk_kernel<<<BATCH, 1024>>>();
    gather_kernel<<<BATCH * (TOPK / 8), 256>>>(feat, W1, b1, W2, b2, out);
}